// round 4
// baseline (speedup 1.0000x reference)
#include <cuda_runtime.h>

// LSTM (H=64, in=1, T=1024, B=4096) + Linear(64->30), fp32.
// 147 blocks (1/SM), 256 threads:
//   khalf = tid&1      : k half (32 of 64 hidden values)
//   j     = (tid>>1)&63: hidden unit -> gate rows {j,64+j,128+j,192+j}
//   bhalf = tid>>7     : which 14 of 28 batches
// Per iteration s: matvec partials for batch s, shfl.bfly(1) exchange; both
// pair lanes then hold identical full gates and redundantly update c/h for
// batch s INLINE (hidden under the next iterations' FFMA2 stream). No
// separate update phase, no gq buffer. x/bias folded into khalf0's init only.
// h and x ping-pong buffered -> one __syncthreads per step.

#define HID      64
#define SEQ_T    1024
#define NBATCH   4096
#define NFC      30
#define NB       28
#define NTHREADS 256
#define XCHUNK   32
#define BPT      14       // batches per thread (updated redundantly by pair)

__device__ __forceinline__ float fast_ex2(float x) {
    float r; asm("ex2.approx.f32 %0, %1;" : "=f"(r) : "f"(x)); return r;
}
__device__ __forceinline__ float fast_rcp(float x) {
    float r; asm("rcp.approx.f32 %0, %1;" : "=f"(r) : "f"(x)); return r;
}
__device__ __forceinline__ float sigm(float x) {
    return fast_rcp(1.0f + fast_ex2(-1.4426950408889634f * x));
}
__device__ __forceinline__ float tanh_fast(float x) {
    return 1.0f - 2.0f * fast_rcp(1.0f + fast_ex2(2.8853900817779268f * x));
}

__device__ __forceinline__ unsigned long long pack2(float lo, float hi) {
    unsigned long long r;
    asm("mov.b64 %0, {%1, %2};" : "=l"(r) : "f"(lo), "f"(hi));
    return r;
}
__device__ __forceinline__ void unpack2(unsigned long long v, float& lo, float& hi) {
    asm("mov.b64 {%0, %1}, %2;" : "=f"(lo), "=f"(hi) : "l"(v));
}
__device__ __forceinline__ void ffma2(unsigned long long& d,
                                      unsigned long long a,
                                      unsigned long long b) {
    asm("fma.rn.f32x2 %0, %1, %2, %0;" : "+l"(d) : "l"(a), "l"(b));
}

__global__ void __launch_bounds__(NTHREADS, 1)
lstm_fused(const float* __restrict__ x,      // [B, T]
           const float* __restrict__ W_ih,   // [256]
           const float* __restrict__ W_hh,   // [256, 64]
           const float* __restrict__ b_ih,   // [256]
           const float* __restrict__ b_hh,   // [256]
           const float* __restrict__ fc_W,   // [30, 64]
           const float* __restrict__ fc_b,   // [30]
           float* __restrict__ out)          // [B, 30]
{
    __shared__ __align__(16) float h_sm[2][NB][HID];     // ping-pong hidden
    __shared__ __align__(16) float x_sm[2][NB][XCHUNK];  // ping-pong x chunks
    __shared__ __align__(16) float fcW_sm[NFC][HID];
    __shared__ float fcb_sm[NFC];

    const int tid   = threadIdx.x;
    const int khalf = tid & 1;          // k half: 0 -> k[0..31], 1 -> k[32..63]
    const int j     = (tid >> 1) & 63;  // hidden unit
    const int bhalf = tid >> 7;         // batch half (0/1)
    const int b0    = blockIdx.x * NB;

    // --- weights: 4 gate rows, my 32 k-values, rotated chunk order so the
    //     two khalves hit disjoint smem bank quads ---
    const int rI = j, rF = HID + j, rG = 2 * HID + j, rO = 3 * HID + j;
    unsigned long long wI[16], wF[16], wG[16], wO[16];
    int hoff[8];  // byte offsets into an h row for chunk i
#pragma unroll
    for (int i = 0; i < 8; ++i) {
        int kb = khalf * 32 + (((i + khalf) & 7) << 2);
        hoff[i] = kb * 4;
        wI[2*i]   = pack2(W_hh[rI*HID + kb],     W_hh[rI*HID + kb + 1]);
        wI[2*i+1] = pack2(W_hh[rI*HID + kb + 2], W_hh[rI*HID + kb + 3]);
        wF[2*i]   = pack2(W_hh[rF*HID + kb],     W_hh[rF*HID + kb + 1]);
        wF[2*i+1] = pack2(W_hh[rF*HID + kb + 2], W_hh[rF*HID + kb + 3]);
        wG[2*i]   = pack2(W_hh[rG*HID + kb],     W_hh[rG*HID + kb + 1]);
        wG[2*i+1] = pack2(W_hh[rG*HID + kb + 2], W_hh[rG*HID + kb + 3]);
        wO[2*i]   = pack2(W_hh[rO*HID + kb],     W_hh[rO*HID + kb + 1]);
        wO[2*i+1] = pack2(W_hh[rO*HID + kb + 2], W_hh[rO*HID + kb + 3]);
    }
    const float wihI = W_ih[rI], wihF = W_ih[rF], wihG = W_ih[rG], wihO = W_ih[rO];
    const float bI = b_ih[rI] + b_hh[rI];
    const float bF = b_ih[rF] + b_hh[rF];
    const float bG = b_ih[rG] + b_hh[rG];
    const float bO = b_ih[rO] + b_hh[rO];

    // --- FC weights to smem; h buf0 zero; x buf0 prologue (t=0..31) ---
    for (int i = tid; i < NFC * HID; i += NTHREADS)
        (&fcW_sm[0][0])[i] = fc_W[i];
    for (int i = tid; i < NFC; i += NTHREADS)
        fcb_sm[i] = fc_b[i];
    for (int i = tid; i < NB * HID; i += NTHREADS)
        (&h_sm[0][0][0])[i] = 0.0f;
    for (int i = tid; i < NB * XCHUNK; i += NTHREADS) {
        int b  = i / XCHUNK;
        int tt = i % XCHUNK;
        int gb = b0 + b; if (gb >= NBATCH) gb = NBATCH - 1;
        (&x_sm[0][0][0])[i] = x[gb * SEQ_T + tt];
    }

    float c_reg[BPT];
#pragma unroll
    for (int s = 0; s < BPT; ++s) c_reg[s] = 0.0f;

    for (int t = 0; t < SEQ_T; ++t) {
        const int rb = t & 1;           // h read buffer
        const int wb = rb ^ 1;          // h write buffer
        const int xb = (t >> 5) & 1;    // x read buffer

        // prefetch NEXT x chunk into the other buffer
        if ((t & (XCHUNK - 1)) == 0 && t + XCHUNK < SEQ_T) {
            for (int i = tid; i < NB * XCHUNK; i += NTHREADS) {
                int b  = i / XCHUNK;
                int tt = i % XCHUNK;
                int gb = b0 + b; if (gb >= NBATCH) gb = NBATCH - 1;
                (&x_sm[xb ^ 1][0][0])[i] = x[gb * SEQ_T + t + XCHUNK + tt];
            }
        }
        __syncthreads();  // h[rb] from prev step + x visible

        const int tx = t & (XCHUNK - 1);

#pragma unroll
        for (int s = 0; s < BPT; ++s) {
            const int b = bhalf * BPT + s;
            const char* hbase = (const char*)&h_sm[rb][b][0];

            // khalf0 seeds its partial with the x/bias term; khalf1 seeds 0,
            // so the pairwise sum counts it exactly once.
            const float xv = x_sm[xb][b][tx];
            unsigned long long aI, aF, aG, aO;
            if (khalf == 0) {
                aI = pack2(fmaf(xv, wihI, bI), 0.0f);
                aF = pack2(fmaf(xv, wihF, bF), 0.0f);
                aG = pack2(fmaf(xv, wihG, bG), 0.0f);
                aO = pack2(fmaf(xv, wihO, bO), 0.0f);
            } else {
                aI = 0ull; aF = 0ull; aG = 0ull; aO = 0ull;
            }
#pragma unroll
            for (int i = 0; i < 8; ++i) {
                ulonglong2 hv = *(const ulonglong2*)(hbase + hoff[i]);
                ffma2(aI, wI[2*i], hv.x); ffma2(aI, wI[2*i+1], hv.y);
                ffma2(aF, wF[2*i], hv.x); ffma2(aF, wF[2*i+1], hv.y);
                ffma2(aG, wG[2*i], hv.x); ffma2(aG, wG[2*i+1], hv.y);
                ffma2(aO, wO[2*i], hv.x); ffma2(aO, wO[2*i+1], hv.y);
            }
            float lo, hi, pI, pF, pG, pO;
            unpack2(aI, lo, hi); pI = lo + hi;
            unpack2(aF, lo, hi); pF = lo + hi;
            unpack2(aG, lo, hi); pG = lo + hi;
            unpack2(aO, lo, hi); pO = lo + hi;

            // exchange with paired lane (lane ^ 1); both lanes end with
            // bitwise-identical full gates (fp add is commutative).
            unsigned long long p01 = pack2(pI, pF);
            unsigned long long p23 = pack2(pG, pO);
            unsigned long long o01 = __shfl_xor_sync(0xffffffffu, p01, 1);
            unsigned long long o23 = __shfl_xor_sync(0xffffffffu, p23, 1);
            float oI, oF, oG, oO;
            unpack2(o01, oI, oF);
            unpack2(o23, oG, oO);

            const float gI = pI + oI;
            const float gF = pF + oF;
            const float gG = pG + oG;
            const float gO = pO + oO;

            // inline pointwise update (redundant in both pair lanes; hidden
            // under subsequent iterations' FFMA2 stream)
            float ci = fmaf(sigm(gF), c_reg[s], sigm(gI) * tanh_fast(gG));
            c_reg[s] = ci;
            h_sm[wb][b][j] = sigm(gO) * tanh_fast(ci);  // both lanes: same value
        }
    }

    __syncthreads();  // final h (buffer 0: last write was t=1023 -> wb=0) ready

    // ---- FC: out[b, f] = h[b,:] . fc_W[f,:] + fc_b[f] ----
    for (int task = tid; task < NB * NFC; task += NTHREADS) {
        int b = task / NFC;
        int f = task % NFC;
        int gb = b0 + b;
        if (gb < NBATCH) {
            float s = fcb_sm[f];
#pragma unroll
            for (int k = 0; k < HID; ++k)
                s = fmaf(h_sm[0][b][k], fcW_sm[f][k], s);
            out[gb * NFC + f] = s;
        }
    }
}

extern "C" void kernel_launch(void* const* d_in, const int* in_sizes, int n_in,
                              void* d_out, int out_size) {
    const float* x    = (const float*)d_in[0];
    const float* W_ih = (const float*)d_in[1];
    const float* W_hh = (const float*)d_in[2];
    const float* b_ih = (const float*)d_in[3];
    const float* b_hh = (const float*)d_in[4];
    const float* fc_W = (const float*)d_in[5];
    const float* fc_b = (const float*)d_in[6];
    (void)in_sizes; (void)n_in; (void)out_size;

    const int grid = (NBATCH + NB - 1) / NB;  // 147 blocks, 1 per SM
    lstm_fused<<<grid, NTHREADS>>>(x, W_ih, W_hh, b_ih, b_hh, fc_W, fc_b,
                                   (float*)d_out);
}

// round 5
// speedup vs baseline: 1.2734x; 1.2734x over previous
#include <cuda_runtime.h>

// LSTM (H=64, in=1, T=1024, B=4096) + Linear(64->30), fp32.
// 147 blocks (1/SM), 256 threads:
//   khalf = tid&1      : k half (32 of 64 hidden values)
//   j     = (tid>>1)&63: hidden unit -> gate rows {j,64+j,128+j,192+j}
//   bhalf = tid>>7     : which 14 of 28 batches
// R3 structure (independent matvec iterations, shfl.bfly(1) pair-combine)
// plus distance-2 software pipelining: iteration s issues the pointwise
// update of batch s-2 (gates long resolved in registers), so MUFU/update
// work dual-issues under the FFMA2 stream instead of forming an exposed
// phase. Both pair lanes update redundantly (bitwise identical; zero extra
// warp issue slots). One __syncthreads per step; h and x ping-pong buffered.

#define HID      64
#define SEQ_T    1024
#define NBATCH   4096
#define NFC      30
#define NB       28
#define NTHREADS 256
#define XCHUNK   32
#define BPT      14       // batches per thread pair

__device__ __forceinline__ float fast_ex2(float x) {
    float r; asm("ex2.approx.f32 %0, %1;" : "=f"(r) : "f"(x)); return r;
}
__device__ __forceinline__ float fast_rcp(float x) {
    float r; asm("rcp.approx.f32 %0, %1;" : "=f"(r) : "f"(x)); return r;
}
__device__ __forceinline__ float sigm(float x) {
    return fast_rcp(1.0f + fast_ex2(-1.4426950408889634f * x));
}
__device__ __forceinline__ float tanh_fast(float x) {
    return 1.0f - 2.0f * fast_rcp(1.0f + fast_ex2(2.8853900817779268f * x));
}

__device__ __forceinline__ unsigned long long pack2(float lo, float hi) {
    unsigned long long r;
    asm("mov.b64 %0, {%1, %2};" : "=l"(r) : "f"(lo), "f"(hi));
    return r;
}
__device__ __forceinline__ void unpack2(unsigned long long v, float& lo, float& hi) {
    asm("mov.b64 {%0, %1}, %2;" : "=f"(lo), "=f"(hi) : "l"(v));
}
__device__ __forceinline__ void ffma2(unsigned long long& d,
                                      unsigned long long a,
                                      unsigned long long b) {
    asm("fma.rn.f32x2 %0, %1, %2, %0;" : "+l"(d) : "l"(a), "l"(b));
}

__global__ void __launch_bounds__(NTHREADS, 1)
lstm_fused(const float* __restrict__ x,      // [B, T]
           const float* __restrict__ W_ih,   // [256]
           const float* __restrict__ W_hh,   // [256, 64]
           const float* __restrict__ b_ih,   // [256]
           const float* __restrict__ b_hh,   // [256]
           const float* __restrict__ fc_W,   // [30, 64]
           const float* __restrict__ fc_b,   // [30]
           float* __restrict__ out)          // [B, 30]
{
    __shared__ __align__(16) float h_sm[2][NB][HID];     // ping-pong hidden
    __shared__ __align__(16) float x_sm[2][NB][XCHUNK];  // ping-pong x chunks
    __shared__ __align__(16) float fcW_sm[NFC][HID];
    __shared__ float fcb_sm[NFC];

    const int tid   = threadIdx.x;
    const int khalf = tid & 1;          // k half: 0 -> k[0..31], 1 -> k[32..63]
    const int j     = (tid >> 1) & 63;  // hidden unit
    const int bhalf = tid >> 7;         // batch half (0/1)
    const int b0    = blockIdx.x * NB;
    const int bbase = bhalf * BPT;      // first local batch for this thread

    // --- weights: 4 gate rows, my 32 k-values, rotated chunk order so the
    //     two khalves hit disjoint smem bank quads ---
    const int rI = j, rF = HID + j, rG = 2 * HID + j, rO = 3 * HID + j;
    unsigned long long wI[16], wF[16], wG[16], wO[16];
    int hoff[8];  // byte offsets into an h row for chunk i
#pragma unroll
    for (int i = 0; i < 8; ++i) {
        int kb = khalf * 32 + (((i + khalf) & 7) << 2);
        hoff[i] = kb * 4;
        wI[2*i]   = pack2(W_hh[rI*HID + kb],     W_hh[rI*HID + kb + 1]);
        wI[2*i+1] = pack2(W_hh[rI*HID + kb + 2], W_hh[rI*HID + kb + 3]);
        wF[2*i]   = pack2(W_hh[rF*HID + kb],     W_hh[rF*HID + kb + 1]);
        wF[2*i+1] = pack2(W_hh[rF*HID + kb + 2], W_hh[rF*HID + kb + 3]);
        wG[2*i]   = pack2(W_hh[rG*HID + kb],     W_hh[rG*HID + kb + 1]);
        wG[2*i+1] = pack2(W_hh[rG*HID + kb + 2], W_hh[rG*HID + kb + 3]);
        wO[2*i]   = pack2(W_hh[rO*HID + kb],     W_hh[rO*HID + kb + 1]);
        wO[2*i+1] = pack2(W_hh[rO*HID + kb + 2], W_hh[rO*HID + kb + 3]);
    }
    const float wihI = W_ih[rI], wihF = W_ih[rF], wihG = W_ih[rG], wihO = W_ih[rO];
    const float bI = b_ih[rI] + b_hh[rI];
    const float bF = b_ih[rF] + b_hh[rF];
    const float bG = b_ih[rG] + b_hh[rG];
    const float bO = b_ih[rO] + b_hh[rO];

    // --- FC weights to smem; h buf0 zero; x buf0 prologue (t=0..31) ---
    for (int i = tid; i < NFC * HID; i += NTHREADS)
        (&fcW_sm[0][0])[i] = fc_W[i];
    for (int i = tid; i < NFC; i += NTHREADS)
        fcb_sm[i] = fc_b[i];
    for (int i = tid; i < NB * HID; i += NTHREADS)
        (&h_sm[0][0][0])[i] = 0.0f;
    for (int i = tid; i < NB * XCHUNK; i += NTHREADS) {
        int b  = i / XCHUNK;
        int tt = i % XCHUNK;
        int gb = b0 + b; if (gb >= NBATCH) gb = NBATCH - 1;
        (&x_sm[0][0][0])[i] = x[gb * SEQ_T + tt];
    }

    float c_reg[BPT];
#pragma unroll
    for (int s = 0; s < BPT; ++s) c_reg[s] = 0.0f;

    for (int t = 0; t < SEQ_T; ++t) {
        const int rb = t & 1;           // h read buffer
        const int wb = rb ^ 1;          // h write buffer
        const int xb = (t >> 5) & 1;    // x read buffer

        if ((t & (XCHUNK - 1)) == 0 && t + XCHUNK < SEQ_T) {
            for (int i = tid; i < NB * XCHUNK; i += NTHREADS) {
                int b  = i / XCHUNK;
                int tt = i % XCHUNK;
                int gb = b0 + b; if (gb >= NBATCH) gb = NBATCH - 1;
                (&x_sm[xb ^ 1][0][0])[i] = x[gb * SEQ_T + t + XCHUNK + tt];
            }
        }
        __syncthreads();  // h[rb] from prev step + x visible

        const int tx = t & (XCHUNK - 1);
        float ring[2][4];  // gates of batches s-2 (ring[s&1]) and s-1

#pragma unroll
        for (int s = 0; s < BPT; ++s) {
            // ---- pipelined update of batch s-2 (gates resolved 2 iters ago;
            //      redundant in both pair lanes, bitwise identical) ----
            if (s >= 2) {
                const int u = s - 2;
                float* g = ring[s & 1];
                float ci = fmaf(sigm(g[1]), c_reg[u], sigm(g[0]) * tanh_fast(g[2]));
                c_reg[u] = ci;
                h_sm[wb][bbase + u][j] = sigm(g[3]) * tanh_fast(ci);
            }

            // ---- matvec partials for batch s ----
            const int b = bbase + s;
            const char* hbase = (const char*)&h_sm[rb][b][0];
            unsigned long long aI = 0ull, aF = 0ull, aG = 0ull, aO = 0ull;
#pragma unroll
            for (int i = 0; i < 8; ++i) {
                ulonglong2 hv = *(const ulonglong2*)(hbase + hoff[i]);
                ffma2(aI, wI[2*i], hv.x); ffma2(aI, wI[2*i+1], hv.y);
                ffma2(aF, wF[2*i], hv.x); ffma2(aF, wF[2*i+1], hv.y);
                ffma2(aG, wG[2*i], hv.x); ffma2(aG, wG[2*i+1], hv.y);
                ffma2(aO, wO[2*i], hv.x); ffma2(aO, wO[2*i+1], hv.y);
            }
            float lo, hi, pI, pF, pG, pO;
            unpack2(aI, lo, hi); pI = lo + hi;
            unpack2(aF, lo, hi); pF = lo + hi;
            unpack2(aG, lo, hi); pG = lo + hi;
            unpack2(aO, lo, hi); pO = lo + hi;

            // pair-combine (lane ^ 1); sum is commutative -> both lanes
            // end with bitwise-identical full gates
            unsigned long long p01 = pack2(pI, pF);
            unsigned long long p23 = pack2(pG, pO);
            unsigned long long o01 = __shfl_xor_sync(0xffffffffu, p01, 1);
            unsigned long long o23 = __shfl_xor_sync(0xffffffffu, p23, 1);
            float oI, oF, oG, oO;
            unpack2(o01, oI, oF);
            unpack2(o23, oG, oO);

            const float xv = x_sm[xb][b][tx];
            float* g = ring[s & 1];
            g[0] = pI + oI + fmaf(xv, wihI, bI);
            g[1] = pF + oF + fmaf(xv, wihF, bF);
            g[2] = pG + oG + fmaf(xv, wihG, bG);
            g[3] = pO + oO + fmaf(xv, wihO, bO);
        }

        // ---- epilogue: updates for batches BPT-2, BPT-1 ----
#pragma unroll
        for (int e = 0; e < 2; ++e) {
            const int u = BPT - 2 + e;
            float* g = ring[u & 1];
            float ci = fmaf(sigm(g[1]), c_reg[u], sigm(g[0]) * tanh_fast(g[2]));
            c_reg[u] = ci;
            h_sm[wb][bbase + u][j] = sigm(g[3]) * tanh_fast(ci);
        }
    }

    __syncthreads();  // final h (buffer 0, SEQ_T even) ready

    // ---- FC: out[b, f] = h[b,:] . fc_W[f,:] + fc_b[f] ----
    for (int task = tid; task < NB * NFC; task += NTHREADS) {
        int b = task / NFC;
        int f = task % NFC;
        int gb = b0 + b;
        if (gb < NBATCH) {
            float s = fcb_sm[f];
#pragma unroll
            for (int k = 0; k < HID; ++k)
                s = fmaf(h_sm[0][b][k], fcW_sm[f][k], s);
            out[gb * NFC + f] = s;
        }
    }
}

extern "C" void kernel_launch(void* const* d_in, const int* in_sizes, int n_in,
                              void* d_out, int out_size) {
    const float* x    = (const float*)d_in[0];
    const float* W_ih = (const float*)d_in[1];
    const float* W_hh = (const float*)d_in[2];
    const float* b_ih = (const float*)d_in[3];
    const float* b_hh = (const float*)d_in[4];
    const float* fc_W = (const float*)d_in[5];
    const float* fc_b = (const float*)d_in[6];
    (void)in_sizes; (void)n_in; (void)out_size;

    const int grid = (NBATCH + NB - 1) / NB;  // 147 blocks, 1 per SM
    lstm_fused<<<grid, NTHREADS>>>(x, W_ih, W_hh, b_ih, b_hh, fc_W, fc_b,
                                   (float*)d_out);
}

// round 6
// speedup vs baseline: 1.3076x; 1.0268x over previous
#include <cuda_runtime.h>

// LSTM (H=64, in=1, T=1024, B=4096) + Linear(64->30), fp32.
// BARRIER-FREE time loop. 147 blocks x 128 threads (4 warps). Each warp
// exclusively owns 7 batch sequences (h, c, x warp-private -> __syncwarp
// only). Lane l handles gate rows {l+32q, q=0..7} = gates i,f,g,o of hidden
// units j=l and j=l+32, full k=64. W_hh lives in smem as [k-chunk][row]
// float4 (lanes stride 16B -> conflict-free LDS.128); packed fma.rn.f32x2
// matvec; h chunk reads are broadcast LDS.128. Warps free-run their 1024
// steps and anti-phase: one warp's MUFU/update overlaps another's FFMA2.

#define HID      64
#define SEQ_T    1024
#define NBATCH   4096
#define NFC      30
#define NB       28
#define NTHREADS 128
#define BPW      7        // batches per warp
#define XCHUNK   32
#define NROW     256      // 4*HID gate rows

__device__ __forceinline__ float fast_ex2(float x) {
    float r; asm("ex2.approx.f32 %0, %1;" : "=f"(r) : "f"(x)); return r;
}
__device__ __forceinline__ float fast_rcp(float x) {
    float r; asm("rcp.approx.f32 %0, %1;" : "=f"(r) : "f"(x)); return r;
}
__device__ __forceinline__ float sigm(float x) {
    return fast_rcp(1.0f + fast_ex2(-1.4426950408889634f * x));
}
__device__ __forceinline__ float tanh_fast(float x) {
    return 1.0f - 2.0f * fast_rcp(1.0f + fast_ex2(2.8853900817779268f * x));
}
__device__ __forceinline__ void unpack2(unsigned long long v, float& lo, float& hi) {
    asm("mov.b64 {%0, %1}, %2;" : "=f"(lo), "=f"(hi) : "l"(v));
}
__device__ __forceinline__ void ffma2(unsigned long long& d,
                                      unsigned long long a,
                                      unsigned long long b) {
    asm("fma.rn.f32x2 %0, %1, %2, %0;" : "+l"(d) : "l"(a), "l"(b));
}

struct Smem {
    float4 w4[16][NROW];      // [k-chunk][gate-row], 64KB, 16B-aligned
    float  h[2][NB][HID];     // ping-pong hidden (warp-private slices)
    float  x[2][NB][XCHUNK];  // ping-pong x chunks (warp-private slices)
    float  fcW[NFC][HID];
    float  fcb[32];
};

extern __shared__ char smem_raw[];

__global__ void __launch_bounds__(NTHREADS, 1)
lstm_fused(const float* __restrict__ x,      // [B, T]
           const float* __restrict__ W_ih,   // [256]
           const float* __restrict__ W_hh,   // [256, 64]
           const float* __restrict__ b_ih,   // [256]
           const float* __restrict__ b_hh,   // [256]
           const float* __restrict__ fc_W,   // [30, 64]
           const float* __restrict__ fc_b,   // [30]
           float* __restrict__ out)          // [B, 30]
{
    Smem* sm = (Smem*)smem_raw;
    const int tid  = threadIdx.x;
    const int lane = tid & 31;
    const int wid  = tid >> 5;
    const int b0   = blockIdx.x * NB;

    // ---- prologue: pack W_hh into smem [chunk][row]; FC weights ----
    for (int idx = tid; idx < 16 * NROW; idx += NTHREADS) {
        int c = idx >> 8;          // chunk 0..15 (NROW=256)
        int row = idx & 255;
        const float* wr = W_hh + row * HID + c * 4;
        sm->w4[c][row] = make_float4(wr[0], wr[1], wr[2], wr[3]);
    }
    for (int i = tid; i < NFC * HID; i += NTHREADS)
        (&sm->fcW[0][0])[i] = fc_W[i];
    for (int i = tid; i < NFC; i += NTHREADS)
        sm->fcb[i] = fc_b[i];
    __syncthreads();  // ONLY block-wide barrier

    const int bloc = wid * BPW;    // first local batch of this warp

    // per-lane row constants: rows lane+32q
    float wih[8], bias[8];
#pragma unroll
    for (int q = 0; q < 8; ++q) {
        int r = lane + 32 * q;
        wih[q]  = W_ih[r];
        bias[q] = b_ih[r] + b_hh[r];
    }

    // warp-private init: h buf0 zero; x chunk 0
#pragma unroll
    for (int b = 0; b < BPW; ++b) {
        sm->h[0][bloc + b][lane]      = 0.0f;
        sm->h[0][bloc + b][lane + 32] = 0.0f;
        int gb = b0 + bloc + b; if (gb >= NBATCH) gb = NBATCH - 1;
        sm->x[0][bloc + b][lane] = x[gb * SEQ_T + lane];
    }
    float c0[BPW], c1[BPW];
#pragma unroll
    for (int b = 0; b < BPW; ++b) { c0[b] = 0.0f; c1[b] = 0.0f; }
    __syncwarp();

    for (int t = 0; t < SEQ_T; ++t) {
        const int rb = t & 1, wb = rb ^ 1, xb = (t >> 5) & 1;

        // warp-private x prefetch, one chunk ahead
        if ((t & (XCHUNK - 1)) == 0 && t + XCHUNK < SEQ_T) {
#pragma unroll
            for (int b = 0; b < BPW; ++b) {
                int gb = b0 + bloc + b; if (gb >= NBATCH) gb = NBATCH - 1;
                sm->x[xb ^ 1][bloc + b][lane] = x[gb * SEQ_T + t + XCHUNK + lane];
            }
        }

        // ---- matvec: acc[q][b] over k chunks ----
        unsigned long long acc[8][BPW];
#pragma unroll
        for (int q = 0; q < 8; ++q)
#pragma unroll
            for (int b = 0; b < BPW; ++b) acc[q][b] = 0ull;

#pragma unroll 4
        for (int c = 0; c < 16; ++c) {
            ulonglong2 w[8];
#pragma unroll
            for (int q = 0; q < 8; ++q)
                w[q] = *(const ulonglong2*)&sm->w4[c][lane + 32 * q];
#pragma unroll
            for (int b = 0; b < BPW; ++b) {
                ulonglong2 hv = *(const ulonglong2*)&sm->h[rb][bloc + b][c * 4];
#pragma unroll
                for (int q = 0; q < 8; ++q) {
                    ffma2(acc[q][b], w[q].x, hv.x);
                    ffma2(acc[q][b], w[q].y, hv.y);
                }
            }
        }

        // ---- gates + pointwise update (warp-private) ----
        const int tx = t & (XCHUNK - 1);
#pragma unroll
        for (int b = 0; b < BPW; ++b) {
            const float xv = sm->x[xb][bloc + b][tx];
            float g[8];
#pragma unroll
            for (int q = 0; q < 8; ++q) {
                float lo, hi; unpack2(acc[q][b], lo, hi);
                g[q] = lo + hi + fmaf(xv, wih[q], bias[q]);
            }
            // j=lane:    i=g[0] f=g[2] g=g[4] o=g[6]
            // j=lane+32: i=g[1] f=g[3] g=g[5] o=g[7]
            float ca = fmaf(sigm(g[2]), c0[b], sigm(g[0]) * tanh_fast(g[4]));
            c0[b] = ca;
            sm->h[wb][bloc + b][lane]      = sigm(g[6]) * tanh_fast(ca);
            float cb = fmaf(sigm(g[3]), c1[b], sigm(g[1]) * tanh_fast(g[5]));
            c1[b] = cb;
            sm->h[wb][bloc + b][lane + 32] = sigm(g[7]) * tanh_fast(cb);
        }
        __syncwarp();   // cross-lane h visibility for next step
    }

    // ---- FC (final h in buffer 0, SEQ_T even): lane f < 30 ----
    if (lane < NFC) {
#pragma unroll
        for (int b = 0; b < BPW; ++b) {
            int gb = b0 + bloc + b;
            if (gb < NBATCH) {
                float s = sm->fcb[lane];
#pragma unroll
                for (int k = 0; k < HID; ++k)
                    s = fmaf(sm->h[0][bloc + b][k], sm->fcW[lane][k], s);
                out[gb * NFC + lane] = s;
            }
        }
    }
}

extern "C" void kernel_launch(void* const* d_in, const int* in_sizes, int n_in,
                              void* d_out, int out_size) {
    const float* x    = (const float*)d_in[0];
    const float* W_ih = (const float*)d_in[1];
    const float* W_hh = (const float*)d_in[2];
    const float* b_ih = (const float*)d_in[3];
    const float* b_hh = (const float*)d_in[4];
    const float* fc_W = (const float*)d_in[5];
    const float* fc_b = (const float*)d_in[6];
    (void)in_sizes; (void)n_in; (void)out_size;

    static_assert(sizeof(Smem) < 100 * 1024, "smem budget");
    cudaFuncSetAttribute(lstm_fused, cudaFuncAttributeMaxDynamicSharedMemorySize,
                         (int)sizeof(Smem));

    const int grid = (NBATCH + NB - 1) / NB;  // 147 blocks, 1 per SM
    lstm_fused<<<grid, NTHREADS, sizeof(Smem)>>>(x, W_ih, W_hh, b_ih, b_hh,
                                                 fc_W, fc_b, (float*)d_out);
}

// round 8
// speedup vs baseline: 1.5140x; 1.1578x over previous
#include <cuda_runtime.h>

// LSTM (H=64, in=1, T=1024, B=4096) + Linear(64->30), fp32.
// Barrier-free time loop with 2 warps/SMSP. 147 blocks x 256 threads
// (8 warps). Warps 0-3 own 4 batches, warps 4-7 own 3 (total 28); SMSP k
// hosts warps {k, k+4} -> 7 batches/SMSP (same FMA floor as R3) but no
// __syncthreads in the loop: co-resident warps anti-phase and hide each
// other's LDS/MUFU latency. Lane l handles gate rows {l+32q, q=0..7}
// (gates i,f,g,o of hidden units j=l and j=l+32). W_hh in smem as
// [k-chunk][row] float4 (base + immediate offsets, conflict-free LDS.128);
// h/x warp-private ping-pong; c in registers; fma.rn.f32x2 matvec.

#define HID      64
#define SEQ_T    1024
#define NBATCH   4096
#define NFC      30
#define NB       28
#define NTHREADS 256
#define XCHUNK   32
#define NROW     256      // 4*HID gate rows

__device__ __forceinline__ float fast_ex2(float x) {
    float r; asm("ex2.approx.f32 %0, %1;" : "=f"(r) : "f"(x)); return r;
}
__device__ __forceinline__ float fast_rcp(float x) {
    float r; asm("rcp.approx.f32 %0, %1;" : "=f"(r) : "f"(x)); return r;
}
__device__ __forceinline__ float sigm(float x) {
    return fast_rcp(1.0f + fast_ex2(-1.4426950408889634f * x));
}
__device__ __forceinline__ float tanh_fast(float x) {
    return 1.0f - 2.0f * fast_rcp(1.0f + fast_ex2(2.8853900817779268f * x));
}
__device__ __forceinline__ void unpack2(unsigned long long v, float& lo, float& hi) {
    asm("mov.b64 {%0, %1}, %2;" : "=f"(lo), "=f"(hi) : "l"(v));
}
__device__ __forceinline__ void ffma2(unsigned long long& d,
                                      unsigned long long a,
                                      unsigned long long b) {
    asm("fma.rn.f32x2 %0, %1, %2, %0;" : "+l"(d) : "l"(a), "l"(b));
}

struct Smem {
    float4 w4[16][NROW];      // [k-chunk][gate-row], 64 KB
    float  h[2][NB][HID];     // ping-pong hidden (warp-private slices)
    float  x[2][NB][XCHUNK];  // ping-pong x chunks (warp-private slices)
    float  fcW[NFC][HID];
    float  fcb[32];
};

extern __shared__ char smem_raw[];

template <int BPW>
__device__ __forceinline__ void lstm_warp(
    Smem* sm, const float* __restrict__ x, float* __restrict__ out,
    int lane, int bloc, int b0,
    const float* wih, const float* biasv)
{
    int gbp[BPW];
#pragma unroll
    for (int b = 0; b < BPW; ++b) {
        int gb = b0 + bloc + b;
        gbp[b] = gb >= NBATCH ? NBATCH - 1 : gb;
    }

    float c0[BPW], c1[BPW];
#pragma unroll
    for (int b = 0; b < BPW; ++b) { c0[b] = 0.0f; c1[b] = 0.0f; }

    // init: h buf0 zero, x buf0 chunk 0 (warp-private)
#pragma unroll
    for (int b = 0; b < BPW; ++b) {
        sm->h[0][bloc + b][lane]      = 0.0f;
        sm->h[0][bloc + b][lane + 32] = 0.0f;
        sm->x[0][bloc + b][lane] = x[gbp[b] * SEQ_T + lane];
    }
    __syncwarp();

    const char* wbase = (const char*)&sm->w4[0][lane];  // +c*4096 +q*512

    for (int t = 0; t < SEQ_T; ++t) {
        const int rb = t & 1, wrb = rb ^ 1, xb = (t >> 5) & 1;

        // warp-private x prefetch, one chunk ahead
        if ((t & (XCHUNK - 1)) == 0 && t + XCHUNK < SEQ_T) {
#pragma unroll
            for (int b = 0; b < BPW; ++b)
                sm->x[xb ^ 1][bloc + b][lane] = x[gbp[b] * SEQ_T + t + XCHUNK + lane];
        }

        // ---- matvec: acc[q][b] over 16 k-chunks ----
        unsigned long long acc[8][BPW];
#pragma unroll
        for (int q = 0; q < 8; ++q)
#pragma unroll
            for (int b = 0; b < BPW; ++b) acc[q][b] = 0ull;

        const char* hb = (const char*)&sm->h[rb][bloc][0];  // +b*256 +c*16

#pragma unroll 8
        for (int c = 0; c < 16; ++c) {
            ulonglong2 w[8];
#pragma unroll
            for (int q = 0; q < 8; ++q)
                w[q] = *(const ulonglong2*)(wbase + c * 4096 + q * 512);
#pragma unroll
            for (int b = 0; b < BPW; ++b) {
                ulonglong2 hv = *(const ulonglong2*)(hb + b * 256 + c * 16);
#pragma unroll
                for (int q = 0; q < 8; ++q) {
                    ffma2(acc[q][b], w[q].x, hv.x);
                    ffma2(acc[q][b], w[q].y, hv.y);
                }
            }
        }

        // ---- gates + pointwise update (warp-private) ----
        const int tx = t & (XCHUNK - 1);
#pragma unroll
        for (int b = 0; b < BPW; ++b) {
            const float xv = sm->x[xb][bloc + b][tx];
            float g[8];
#pragma unroll
            for (int q = 0; q < 8; ++q) {
                float lo, hi; unpack2(acc[q][b], lo, hi);
                g[q] = lo + hi + fmaf(xv, wih[q], biasv[q]);
            }
            // j=lane:    i=g[0] f=g[2] g=g[4] o=g[6]
            // j=lane+32: i=g[1] f=g[3] g=g[5] o=g[7]
            float ca = fmaf(sigm(g[2]), c0[b], sigm(g[0]) * tanh_fast(g[4]));
            c0[b] = ca;
            sm->h[wrb][bloc + b][lane]      = sigm(g[6]) * tanh_fast(ca);
            float cb = fmaf(sigm(g[3]), c1[b], sigm(g[1]) * tanh_fast(g[5]));
            c1[b] = cb;
            sm->h[wrb][bloc + b][lane + 32] = sigm(g[7]) * tanh_fast(cb);
        }
        __syncwarp();   // cross-lane h visibility for next step
    }

    // ---- FC (final h in buffer 0, SEQ_T even) ----
    if (lane < NFC) {
#pragma unroll
        for (int b = 0; b < BPW; ++b) {
            int gb = b0 + bloc + b;
            if (gb < NBATCH) {
                float s = sm->fcb[lane];
#pragma unroll
                for (int k = 0; k < HID; ++k)
                    s = fmaf(sm->h[0][bloc + b][k], sm->fcW[lane][k], s);
                out[gb * NFC + lane] = s;
            }
        }
    }
}

__global__ void __launch_bounds__(NTHREADS, 1)
lstm_fused(const float* __restrict__ x,      // [B, T]
           const float* __restrict__ W_ih,   // [256]
           const float* __restrict__ W_hh,   // [256, 64]
           const float* __restrict__ b_ih,   // [256]
           const float* __restrict__ b_hh,   // [256]
           const float* __restrict__ fc_W,   // [30, 64]
           const float* __restrict__ fc_b,   // [30]
           float* __restrict__ out)          // [B, 30]
{
    Smem* sm = (Smem*)smem_raw;
    const int tid  = threadIdx.x;
    const int lane = tid & 31;
    const int wid  = tid >> 5;
    const int b0   = blockIdx.x * NB;

    // ---- prologue: W_hh -> smem [chunk][row]; FC weights ----
    for (int idx = tid; idx < 16 * NROW; idx += NTHREADS) {
        int c = idx >> 8;          // chunk 0..15
        int row = idx & 255;
        const float* wr = W_hh + row * HID + c * 4;
        sm->w4[c][row] = make_float4(wr[0], wr[1], wr[2], wr[3]);
    }
    for (int i = tid; i < NFC * HID; i += NTHREADS)
        (&sm->fcW[0][0])[i] = fc_W[i];
    for (int i = tid; i < NFC; i += NTHREADS)
        sm->fcb[i] = fc_b[i];

    // per-lane row constants: rows lane+32q
    float wih[8], biasv[8];
#pragma unroll
    for (int q = 0; q < 8; ++q) {
        int r = lane + 32 * q;
        wih[q]   = W_ih[r];
        biasv[q] = b_ih[r] + b_hh[r];
    }
    __syncthreads();  // ONLY block-wide barrier

    // batch ownership: warps 0-3 -> 4 batches (bloc 0,4,8,12);
    //                  warps 4-7 -> 3 batches (bloc 16,19,22,25)
    if (wid < 4)
        lstm_warp<4>(sm, x, out, lane, wid * 4, b0, wih, biasv);
    else
        lstm_warp<3>(sm, x, out, lane, 16 + (wid - 4) * 3, b0, wih, biasv);
}

extern "C" void kernel_launch(void* const* d_in, const int* in_sizes, int n_in,
                              void* d_out, int out_size) {
    const float* x    = (const float*)d_in[0];
    const float* W_ih = (const float*)d_in[1];
    const float* W_hh = (const float*)d_in[2];
    const float* b_ih = (const float*)d_in[3];
    const float* b_hh = (const float*)d_in[4];
    const float* fc_W = (const float*)d_in[5];
    const float* fc_b = (const float*)d_in[6];
    (void)in_sizes; (void)n_in; (void)out_size;

    static_assert(sizeof(Smem) < 110 * 1024, "smem budget");
    cudaFuncSetAttribute(lstm_fused, cudaFuncAttributeMaxDynamicSharedMemorySize,
                         (int)sizeof(Smem));

    const int grid = (NBATCH + NB - 1) / NB;  // 147 blocks, 1 per SM
    lstm_fused<<<grid, NTHREADS, sizeof(Smem)>>>(x, W_ih, W_hh, b_ih, b_hh,
                                                 fc_W, fc_b, (float*)d_out);
}

// round 9
// speedup vs baseline: 1.5970x; 1.0549x over previous
#include <cuda_runtime.h>

// LSTM (H=64, in=1, T=1024, B=4096) + Linear(64->30), fp32.
// R3 layout (weights in registers, shfl.bfly pair-combine, ping-pong h/x,
// c in registers) but with GROUP-scoped sync: threads 0-127 (warps 0-3) own
// batches 0-13, threads 128-255 (warps 4-7) own batches 14-27. The time-loop
// barrier is a named barrier per 128-thread group, so the two groups free-run
// and anti-phase: each SMSP hosts one warp of each group, and one group's
// MUFU-heavy update overlaps the other's FFMA2 matvec.
// Thread decomposition within a group:
//   khalf = tid&1      : k half (32 of 64 hidden values)
//   j     = (tid>>1)&63: hidden unit -> gate rows {j,64+j,128+j,192+j}

#define HID      64
#define SEQ_T    1024
#define NBATCH   4096
#define NFC      30
#define NB       28
#define NBG      14       // batches per group
#define NTHREADS 256
#define XCHUNK   32
#define BPT      14       // matvec batches per thread (its group's batches)
#define BOWN     7        // batches owned per thread for c/h update

__device__ __forceinline__ float fast_ex2(float x) {
    float r; asm("ex2.approx.f32 %0, %1;" : "=f"(r) : "f"(x)); return r;
}
__device__ __forceinline__ float fast_rcp(float x) {
    float r; asm("rcp.approx.f32 %0, %1;" : "=f"(r) : "f"(x)); return r;
}
__device__ __forceinline__ float sigm(float x) {
    return fast_rcp(1.0f + fast_ex2(-1.4426950408889634f * x));
}
__device__ __forceinline__ float tanh_fast(float x) {
    return 1.0f - 2.0f * fast_rcp(1.0f + fast_ex2(2.8853900817779268f * x));
}

__device__ __forceinline__ unsigned long long pack2(float lo, float hi) {
    unsigned long long r;
    asm("mov.b64 %0, {%1, %2};" : "=l"(r) : "f"(lo), "f"(hi));
    return r;
}
__device__ __forceinline__ void unpack2(unsigned long long v, float& lo, float& hi) {
    asm("mov.b64 {%0, %1}, %2;" : "=f"(lo), "=f"(hi) : "l"(v));
}
__device__ __forceinline__ void ffma2(unsigned long long& d,
                                      unsigned long long a,
                                      unsigned long long b) {
    asm("fma.rn.f32x2 %0, %1, %2, %0;" : "+l"(d) : "l"(a), "l"(b));
}
// named barrier: 128 threads of one group (ids 1 and 2; 0 is __syncthreads)
__device__ __forceinline__ void group_bar(int id) {
    asm volatile("bar.sync %0, 128;" :: "r"(id) : "memory");
}

__global__ void __launch_bounds__(NTHREADS, 1)
lstm_fused(const float* __restrict__ x,      // [B, T]
           const float* __restrict__ W_ih,   // [256]
           const float* __restrict__ W_hh,   // [256, 64]
           const float* __restrict__ b_ih,   // [256]
           const float* __restrict__ b_hh,   // [256]
           const float* __restrict__ fc_W,   // [30, 64]
           const float* __restrict__ fc_b,   // [30]
           float* __restrict__ out)          // [B, 30]
{
    __shared__ __align__(16) float h_sm[2][NB][HID];     // ping-pong hidden
    __shared__ __align__(16) float x_sm[2][NB][XCHUNK];  // ping-pong x chunks
    __shared__ __align__(16) float fcW_sm[NFC][HID];
    __shared__ float fcb_sm[NFC];

    const int tid   = threadIdx.x;
    const int khalf = tid & 1;          // k half: 0 -> k[0..31], 1 -> k[32..63]
    const int j     = (tid >> 1) & 63;  // hidden unit
    const int grp   = tid >> 7;         // group 0: warps 0-3; group 1: warps 4-7
    const int gtid  = tid & 127;        // thread id within group
    const int barid = 1 + grp;
    const int b0    = blockIdx.x * NB;
    const int bbase = grp * NBG;        // first local batch of this group

    // --- weights: 4 gate rows, my 32 k-values, rotated chunk order so the
    //     two khalves hit disjoint smem bank quads ---
    const int rI = j, rF = HID + j, rG = 2 * HID + j, rO = 3 * HID + j;
    unsigned long long wI[16], wF[16], wG[16], wO[16];
    int hoff[8];  // byte offsets into an h row for chunk i
#pragma unroll
    for (int i = 0; i < 8; ++i) {
        int kb = khalf * 32 + (((i + khalf) & 7) << 2);
        hoff[i] = kb * 4;
        wI[2*i]   = pack2(W_hh[rI*HID + kb],     W_hh[rI*HID + kb + 1]);
        wI[2*i+1] = pack2(W_hh[rI*HID + kb + 2], W_hh[rI*HID + kb + 3]);
        wF[2*i]   = pack2(W_hh[rF*HID + kb],     W_hh[rF*HID + kb + 1]);
        wF[2*i+1] = pack2(W_hh[rF*HID + kb + 2], W_hh[rF*HID + kb + 3]);
        wG[2*i]   = pack2(W_hh[rG*HID + kb],     W_hh[rG*HID + kb + 1]);
        wG[2*i+1] = pack2(W_hh[rG*HID + kb + 2], W_hh[rG*HID + kb + 3]);
        wO[2*i]   = pack2(W_hh[rO*HID + kb],     W_hh[rO*HID + kb + 1]);
        wO[2*i+1] = pack2(W_hh[rO*HID + kb + 2], W_hh[rO*HID + kb + 3]);
    }
    const float wihI = W_ih[rI], wihF = W_ih[rF], wihG = W_ih[rG], wihO = W_ih[rO];
    const float bI = b_ih[rI] + b_hh[rI];
    const float bF = b_ih[rF] + b_hh[rF];
    const float bG = b_ih[rG] + b_hh[rG];
    const float bO = b_ih[rO] + b_hh[rO];

    // --- FC weights to smem; h buf0 zero; x buf0 prologue (t=0..31) ---
    for (int i = tid; i < NFC * HID; i += NTHREADS)
        (&fcW_sm[0][0])[i] = fc_W[i];
    for (int i = tid; i < NFC; i += NTHREADS)
        fcb_sm[i] = fc_b[i];
    for (int i = tid; i < NB * HID; i += NTHREADS)
        (&h_sm[0][0][0])[i] = 0.0f;
    for (int i = tid; i < NB * XCHUNK; i += NTHREADS) {
        int b  = i / XCHUNK;
        int tt = i % XCHUNK;
        int gb = b0 + b; if (gb >= NBATCH) gb = NBATCH - 1;
        (&x_sm[0][0][0])[i] = x[gb * SEQ_T + tt];
    }

    float c_reg[BOWN];
#pragma unroll
    for (int s = 0; s < BOWN; ++s) c_reg[s] = 0.0f;

    __syncthreads();  // only block-wide barrier (prologue)

    for (int t = 0; t < SEQ_T; ++t) {
        const int rb = t & 1;           // h read buffer
        const int wb = rb ^ 1;          // h write buffer
        const int xb = (t >> 5) & 1;    // x read buffer

        // group-private prefetch of NEXT x chunk into the other buffer
        if ((t & (XCHUNK - 1)) == 0 && t + XCHUNK < SEQ_T) {
            for (int i = gtid; i < NBG * XCHUNK; i += 128) {
                int b  = bbase + i / XCHUNK;
                int tt = i % XCHUNK;
                int gb = b0 + b; if (gb >= NBATCH) gb = NBATCH - 1;
                x_sm[xb ^ 1][b][tt] = x[gb * SEQ_T + t + XCHUNK + tt];
            }
        }
        group_bar(barid);  // group's h[rb] writes + x chunk visible

        const int tx = t & (XCHUNK - 1);
        float gq[BOWN][4];  // full gates for the 7 batches this thread owns

#pragma unroll
        for (int s = 0; s < BPT; ++s) {
            const int b = bbase + s;
            const char* hbase = (const char*)&h_sm[rb][b][0];

            unsigned long long aI = 0ull, aF = 0ull, aG = 0ull, aO = 0ull;
#pragma unroll
            for (int i = 0; i < 8; ++i) {
                ulonglong2 hv = *(const ulonglong2*)(hbase + hoff[i]);
                ffma2(aI, wI[2*i], hv.x); ffma2(aI, wI[2*i+1], hv.y);
                ffma2(aF, wF[2*i], hv.x); ffma2(aF, wF[2*i+1], hv.y);
                ffma2(aG, wG[2*i], hv.x); ffma2(aG, wG[2*i+1], hv.y);
                ffma2(aO, wO[2*i], hv.x); ffma2(aO, wO[2*i+1], hv.y);
            }
            float lo, hi, pI, pF, pG, pO;
            unpack2(aI, lo, hi); pI = lo + hi;
            unpack2(aF, lo, hi); pF = lo + hi;
            unpack2(aG, lo, hi); pG = lo + hi;
            unpack2(aO, lo, hi); pO = lo + hi;

            // combine k-halves with the paired lane (lane ^ 1, same warp)
            unsigned long long p01 = pack2(pI, pF);
            unsigned long long p23 = pack2(pG, pO);
            unsigned long long o01 = __shfl_xor_sync(0xffffffffu, p01, 1);
            unsigned long long o23 = __shfl_xor_sync(0xffffffffu, p23, 1);
            float oI, oF, oG, oO;
            unpack2(o01, oI, oF);
            unpack2(o23, oG, oO);

            const float xv = x_sm[xb][b][tx];
            float gI = pI + oI + fmaf(xv, wihI, bI);
            float gF = pF + oF + fmaf(xv, wihF, bF);
            float gG = pG + oG + fmaf(xv, wihG, bG);
            float gO = pO + oO + fmaf(xv, wihO, bO);

            // keep only batches this lane owns: khalf0 -> s 0..6, khalf1 -> 7..13
            if (s < BOWN) {
                if (khalf == 0) { gq[s][0]=gI; gq[s][1]=gF; gq[s][2]=gG; gq[s][3]=gO; }
            } else {
                if (khalf == 1) { gq[s-BOWN][0]=gI; gq[s-BOWN][1]=gF; gq[s-BOWN][2]=gG; gq[s-BOWN][3]=gO; }
            }
        }

        // ---- divergence-free update: each lane updates its 7 owned batches ----
#pragma unroll
        for (int q = 0; q < BOWN; ++q) {
            const int b = bbase + khalf * BOWN + q;
            float ci = fmaf(sigm(gq[q][1]), c_reg[q],
                            sigm(gq[q][0]) * tanh_fast(gq[q][2]));
            c_reg[q] = ci;
            h_sm[wb][b][j] = sigm(gq[q][3]) * tanh_fast(ci);
        }
    }

    group_bar(barid);  // group's final h (buffer 0, SEQ_T even) ready

    // ---- FC (group-private): out[b, f] = h[b,:] . fc_W[f,:] + fc_b[f] ----
    for (int task = gtid; task < NBG * NFC; task += 128) {
        int b = bbase + task / NFC;
        int f = task % NFC;
        int gb = b0 + b;
        if (gb < NBATCH) {
            float s = fcb_sm[f];
#pragma unroll
            for (int k = 0; k < HID; ++k)
                s = fmaf(h_sm[0][b][k], fcW_sm[f][k], s);
            out[gb * NFC + f] = s;
        }
    }
}

extern "C" void kernel_launch(void* const* d_in, const int* in_sizes, int n_in,
                              void* d_out, int out_size) {
    const float* x    = (const float*)d_in[0];
    const float* W_ih = (const float*)d_in[1];
    const float* W_hh = (const float*)d_in[2];
    const float* b_ih = (const float*)d_in[3];
    const float* b_hh = (const float*)d_in[4];
    const float* fc_W = (const float*)d_in[5];
    const float* fc_b = (const float*)d_in[6];
    (void)in_sizes; (void)n_in; (void)out_size;

    const int grid = (NBATCH + NB - 1) / NB;  // 147 blocks, 1 per SM
    lstm_fused<<<grid, NTHREADS>>>(x, W_ih, W_hh, b_ih, b_hh, fc_W, fc_b,
                                   (float*)d_out);
}